// round 3
// baseline (speedup 1.0000x reference)
#include <cuda_runtime.h>
#include <stdint.h>

// InfoNCE loss with exact JAX partitionable threefry2x32-20 sampling.
// bits[p] = x0 ^ x1 of threefry2x32(key=(0,42), counter=(0, p)), p = row*E+col.
// u = bitcast((bits>>9)|0x3F800000)-1 : ordering == ordering of (bits>>9),
// with stable column tie-break (matches double-argsort rank).
//
// kernel 1: one block per row. Streams adj + threefry, collects positives and
//           negative candidates (u < 1/64; ~256 expected, k<=~60 needed),
//           exact rank-select of k = num_pos smallest (key,col), gathers the
//           ~66 entity rows involved, computes per-row loss -> global arrays.
// kernel 2: deterministic reduction -> scalar mean.

#define TEMP   0.07f
#define MAXC   512        // candidate buffer (expected ~256, 16-sigma headroom)
#define MAXP   128        // positives per row (expected ~33)
#define KEYCUT (1u << 17) // (2^23)/64  ->  u < 1/64
#define NROWS  4096

static __device__ double g_rowLoss[NROWS];
static __device__ int    g_rowPairs[NROWS];

__device__ __forceinline__ uint32_t rotl32(uint32_t v, int r) {
    return __funnelshift_l(v, v, r);
}

// Threefry-2x32, 20 rounds, key=(0,42), counter=(0,p). Returns x0out ^ x1out
// (JAX partitionable 32-bit bits = bits1 ^ bits2).
__device__ __forceinline__ uint32_t threefry_bits(uint32_t p) {
    const uint32_t ks1 = 42u;
    const uint32_t ks2 = 0x1BD11BDAu ^ 42u;
    uint32_t x0 = 0u;            // c_hi + ks0 = 0
    uint32_t x1 = p + ks1;       // c_lo + ks1
    // rounds 1-4 (13,15,26,6)
    x0 += x1; x1 = rotl32(x1, 13) ^ x0;
    x0 += x1; x1 = rotl32(x1, 15) ^ x0;
    x0 += x1; x1 = rotl32(x1, 26) ^ x0;
    x0 += x1; x1 = rotl32(x1,  6) ^ x0;
    x0 += ks1; x1 += ks2 + 1u;
    // rounds 5-8 (17,29,16,24)
    x0 += x1; x1 = rotl32(x1, 17) ^ x0;
    x0 += x1; x1 = rotl32(x1, 29) ^ x0;
    x0 += x1; x1 = rotl32(x1, 16) ^ x0;
    x0 += x1; x1 = rotl32(x1, 24) ^ x0;
    x0 += ks2; x1 += 2u;            // + ks0(=0) + 2
    // rounds 9-12 (13,15,26,6)
    x0 += x1; x1 = rotl32(x1, 13) ^ x0;
    x0 += x1; x1 = rotl32(x1, 15) ^ x0;
    x0 += x1; x1 = rotl32(x1, 26) ^ x0;
    x0 += x1; x1 = rotl32(x1,  6) ^ x0;
    /* x0 += ks0 */ x1 += ks1 + 3u;
    // rounds 13-16 (17,29,16,24)
    x0 += x1; x1 = rotl32(x1, 17) ^ x0;
    x0 += x1; x1 = rotl32(x1, 29) ^ x0;
    x0 += x1; x1 = rotl32(x1, 16) ^ x0;
    x0 += x1; x1 = rotl32(x1, 24) ^ x0;
    x0 += ks1; x1 += ks2 + 4u;
    // rounds 17-20 (13,15,26,6)
    x0 += x1; x1 = rotl32(x1, 13) ^ x0;
    x0 += x1; x1 = rotl32(x1, 15) ^ x0;
    x0 += x1; x1 = rotl32(x1, 26) ^ x0;
    x0 += x1; x1 = rotl32(x1,  6) ^ x0;
    x0 += ks2; x1 += 5u;            // + ks0(=0) + 5
    return x0 ^ x1;
}

__global__ __launch_bounds__(256)
void infonce_row(const float* __restrict__ item,
                 const float* __restrict__ ent,
                 const int*   __restrict__ adj,
                 int E)
{
    __shared__ float              s_it[64];         // item row * 1/(||it||*T)
    __shared__ unsigned long long s_cand[MAXC];     // (key32<<32)|col
    __shared__ unsigned short     s_posRaw[MAXP];
    __shared__ unsigned short     s_pos[MAXP];      // positives, sorted by col
    __shared__ unsigned short     s_sel[MAXP];      // selected negs, by rank
    __shared__ float              s_simN[MAXP];
    __shared__ float              s_simP[MAXP];
    __shared__ int                s_np, s_nc;
    __shared__ float              s_mS[2];

    const int tid    = threadIdx.x;
    const int lane   = tid & 31;
    const int warpId = tid >> 5;
    const int row    = blockIdx.x;

    if (tid == 0) { s_np = 0; s_nc = 0; }
    if (tid < 64) s_it[tid] = item[(size_t)row * 64 + tid];
    __syncthreads();
    if (tid < 32) {
        float a = s_it[lane], b = s_it[lane + 32];
        float ss = a * a + b * b;
        #pragma unroll
        for (int o = 16; o; o >>= 1) ss += __shfl_down_sync(0xffffffffu, ss, o);
        ss = __shfl_sync(0xffffffffu, ss, 0);
        float sc = 1.0f / (sqrtf(ss) * TEMP);
        s_it[lane]      = a * sc;
        s_it[lane + 32] = b * sc;
    }
    __syncthreads();

    const uint32_t base = (uint32_t)row * (uint32_t)E;
    const int* adjR = adj + (size_t)row * E;

    // ---- streaming pass: threefry + adj scan (4 independent chains/thread) --
    #pragma unroll 1
    for (int c0 = tid * 4; c0 < E; c0 += 1024) {
        int4 a4 = *(const int4*)(adjR + c0);
        #pragma unroll
        for (int j = 0; j < 4; ++j) {
            uint32_t c   = (uint32_t)c0 + (uint32_t)j;
            uint32_t key = threefry_bits(base + c) >> 9;
            int a = (j==0)?a4.x:(j==1)?a4.y:(j==2)?a4.z:a4.w;
            if (a > 0) {
                int i = atomicAdd(&s_np, 1);
                if (i < MAXP) s_posRaw[i] = (unsigned short)c;
            } else if (key < KEYCUT) {
                int i = atomicAdd(&s_nc, 1);
                if (i < MAXC) s_cand[i] = ((unsigned long long)key << 32) | c;
            }
        }
    }
    __syncthreads();

    const int np   = min(s_np, MAXP);
    const int nc   = min(s_nc, MAXC);
    const int k    = np;               // k = min(num_pos, num_neg) = num_pos
    const int ksel = min(k, nc);

    // exact rank-select: write each of the k smallest (key,col) at its rank
    if (k > 0) {
        for (int idx = tid; idx < nc; idx += 256) {
            unsigned long long v = s_cand[idx];
            int rank = 0;
            for (int j = 0; j < nc; ++j) rank += (s_cand[j] < v);
            if (rank < k) s_sel[rank] = (unsigned short)(v & 0xFFFFu);
        }
    }
    // deterministic positive ordering (sorted by column; cols are unique)
    for (int idx = tid; idx < np; idx += 256) {
        unsigned short c = s_posRaw[idx];
        int rank = 0;
        for (int j = 0; j < np; ++j) rank += (s_posRaw[j] < c);
        s_pos[rank] = c;
    }
    __syncthreads();

    // cosine sims (one warp per entity row)
    for (int s = warpId; s < ksel; s += 8) {
        int col = s_sel[s];
        float2 v = ((const float2*)ent)[(size_t)col * 32 + lane];
        float dot = v.x * s_it[2*lane] + v.y * s_it[2*lane + 1];
        float ssq = v.x * v.x + v.y * v.y;
        #pragma unroll
        for (int o = 16; o; o >>= 1) {
            dot += __shfl_down_sync(0xffffffffu, dot, o);
            ssq += __shfl_down_sync(0xffffffffu, ssq, o);
        }
        if (lane == 0) s_simN[s] = dot / sqrtf(ssq);
    }
    for (int s = warpId; s < np; s += 8) {
        int col = s_pos[s];
        float2 v = ((const float2*)ent)[(size_t)col * 32 + lane];
        float dot = v.x * s_it[2*lane] + v.y * s_it[2*lane + 1];
        float ssq = v.x * v.x + v.y * v.y;
        #pragma unroll
        for (int o = 16; o; o >>= 1) {
            dot += __shfl_down_sync(0xffffffffu, dot, o);
            ssq += __shfl_down_sync(0xffffffffu, ssq, o);
        }
        if (lane == 0) s_simP[s] = dot / sqrtf(ssq);
    }
    __syncthreads();

    // m and S over sampled negatives (warp 0)
    if (warpId == 0 && ksel > 0) {
        float mm = -INFINITY;
        for (int s = lane; s < ksel; s += 32) mm = fmaxf(mm, s_simN[s]);
        #pragma unroll
        for (int o = 16; o; o >>= 1) mm = fmaxf(mm, __shfl_down_sync(0xffffffffu, mm, o));
        mm = __shfl_sync(0xffffffffu, mm, 0);
        float Ss = 0.0f;
        for (int s = lane; s < ksel; s += 32) Ss += expf(s_simN[s] - mm);
        #pragma unroll
        for (int o = 16; o; o >>= 1) Ss += __shfl_down_sync(0xffffffffu, Ss, o);
        if (lane == 0) { s_mS[0] = mm; s_mS[1] = Ss; }
    }
    __syncthreads();

    // per-pair CE, row sum (warp 0)
    if (warpId == 0) {
        float acc = 0.0f;
        if (np > 0 && ksel > 0) {
            float m = s_mS[0], S = s_mS[1];
            for (int i = lane; i < np; i += 32) {
                float sp = s_simP[i];
                float pm = fmaxf(sp, m);
                acc += logf(expf(sp - pm) + S * expf(m - pm)) + pm - sp;
            }
        }
        #pragma unroll
        for (int o = 16; o; o >>= 1) acc += __shfl_down_sync(0xffffffffu, acc, o);
        if (lane == 0) {
            g_rowLoss[row]  = (double)acc;
            g_rowPairs[row] = (np > 0 && ksel > 0) ? np : 0;
        }
    }
}

__global__ void finalize_kernel(float* out, int I) {
    __shared__ double    st[256];
    __shared__ long long sp[256];
    double t = 0.0; long long p = 0;
    for (int i = threadIdx.x; i < I; i += 256) {
        t += g_rowLoss[i];
        p += (long long)g_rowPairs[i];
    }
    st[threadIdx.x] = t; sp[threadIdx.x] = p;
    __syncthreads();
    for (int o = 128; o; o >>= 1) {
        if (threadIdx.x < o) {
            st[threadIdx.x] += st[threadIdx.x + o];
            sp[threadIdx.x] += sp[threadIdx.x + o];
        }
        __syncthreads();
    }
    if (threadIdx.x == 0)
        out[0] = (sp[0] > 0) ? (float)(st[0] / (double)sp[0]) : 0.0f;
}

extern "C" void kernel_launch(void* const* d_in, const int* in_sizes, int n_in,
                              void* d_out, int out_size) {
    const float* item = (const float*)d_in[0];
    const float* ent  = (const float*)d_in[1];
    const int*   adj  = (const int*)d_in[2];
    float* out = (float*)d_out;
    int I = in_sizes[0] / 64;
    int E = in_sizes[1] / 64;
    infonce_row<<<I, 256>>>(item, ent, adj, E);
    finalize_kernel<<<1, 256>>>(out, I);
}

// round 4
// speedup vs baseline: 1.1920x; 1.1920x over previous
#include <cuda_runtime.h>
#include <stdint.h>

// InfoNCE loss with exact JAX partitionable threefry2x32-20 sampling.
// bits[p] = x0 ^ x1 of threefry2x32(key=(0,42), counter=(0, p)), p = row*E+col.
// Single fused kernel: per-row block does RNG+scan+select+loss; the last block
// to finish performs the deterministic global reduction (last-CTA pattern).

#define TEMP    0.07f
#define MAXC    256        // candidate buffer (E[nc]~128 at u<1/128, 11-sigma)
#define MAXP    128        // positives per row (expected ~33)
#define BITSCUT (1u << 25) // bits < 2^25  <=>  u < 1/128
#define NROWS   4096

static __device__ double g_rowLoss[NROWS];
static __device__ int    g_rowPairs[NROWS];
static __device__ unsigned int g_done = 0;

__device__ __forceinline__ uint32_t rotl32(uint32_t v, int r) {
    return __funnelshift_l(v, v, r);
}

// Threefry-2x32, 20 rounds, key=(0,42), counter=(0,p). Returns x0out ^ x1out.
__device__ __forceinline__ uint32_t threefry_bits(uint32_t p) {
    const uint32_t ks1 = 42u;
    const uint32_t ks2 = 0x1BD11BDAu ^ 42u;
    uint32_t x0 = 0u;            // c_hi + ks0 = 0
    uint32_t x1 = p + ks1;       // c_lo + ks1
    x0 += x1; x1 = rotl32(x1, 13) ^ x0;
    x0 += x1; x1 = rotl32(x1, 15) ^ x0;
    x0 += x1; x1 = rotl32(x1, 26) ^ x0;
    x0 += x1; x1 = rotl32(x1,  6) ^ x0;
    x0 += ks1; x1 += ks2 + 1u;
    x0 += x1; x1 = rotl32(x1, 17) ^ x0;
    x0 += x1; x1 = rotl32(x1, 29) ^ x0;
    x0 += x1; x1 = rotl32(x1, 16) ^ x0;
    x0 += x1; x1 = rotl32(x1, 24) ^ x0;
    x0 += ks2; x1 += 2u;
    x0 += x1; x1 = rotl32(x1, 13) ^ x0;
    x0 += x1; x1 = rotl32(x1, 15) ^ x0;
    x0 += x1; x1 = rotl32(x1, 26) ^ x0;
    x0 += x1; x1 = rotl32(x1,  6) ^ x0;
    /* x0 += ks0 */ x1 += ks1 + 3u;
    x0 += x1; x1 = rotl32(x1, 17) ^ x0;
    x0 += x1; x1 = rotl32(x1, 29) ^ x0;
    x0 += x1; x1 = rotl32(x1, 16) ^ x0;
    x0 += x1; x1 = rotl32(x1, 24) ^ x0;
    x0 += ks1; x1 += ks2 + 4u;
    x0 += x1; x1 = rotl32(x1, 13) ^ x0;
    x0 += x1; x1 = rotl32(x1, 15) ^ x0;
    x0 += x1; x1 = rotl32(x1, 26) ^ x0;
    x0 += x1; x1 = rotl32(x1,  6) ^ x0;
    x0 += ks2; x1 += 5u;
    return x0 ^ x1;
}

__global__ __launch_bounds__(256)
void infonce_row(const float* __restrict__ item,
                 const float* __restrict__ ent,
                 const int*   __restrict__ adj,
                 float* __restrict__ out,
                 int E, int I)
{
    __shared__ float              s_it[64];         // item row * 1/(||it||*T)
    __shared__ unsigned long long s_cand[MAXC];     // (key23<<32)|col
    __shared__ unsigned short     s_posRaw[MAXP];
    __shared__ unsigned short     s_pos[MAXP];      // positives, sorted by col
    __shared__ unsigned short     s_sel[MAXP];      // selected negs, by rank
    __shared__ float              s_simN[MAXP];
    __shared__ float              s_simP[MAXP];
    __shared__ int                s_np, s_nc, s_last;
    __shared__ float              s_mS[2];
    __shared__ double             s_red[256];
    __shared__ long long          s_redp[256];

    const int tid    = threadIdx.x;
    const int lane   = tid & 31;
    const int warpId = tid >> 5;
    const int row    = blockIdx.x;

    if (tid == 0) { s_np = 0; s_nc = 0; }
    if (tid < 64) s_it[tid] = item[(size_t)row * 64 + tid];
    __syncthreads();
    if (tid < 32) {
        float a = s_it[lane], b = s_it[lane + 32];
        float ss = a * a + b * b;
        #pragma unroll
        for (int o = 16; o; o >>= 1) ss += __shfl_down_sync(0xffffffffu, ss, o);
        ss = __shfl_sync(0xffffffffu, ss, 0);
        float sc = 1.0f / (sqrtf(ss) * TEMP);
        s_it[lane]      = a * sc;
        s_it[lane + 32] = b * sc;
    }
    __syncthreads();

    const uint32_t base = (uint32_t)row * (uint32_t)E;
    const int* adjR = adj + (size_t)row * E;

    // ---- streaming pass: threefry + adj scan (4 independent chains/thread) --
    #pragma unroll 1
    for (int c0 = tid * 4; c0 < E; c0 += 1024) {
        int4 a4 = *(const int4*)(adjR + c0);
        #pragma unroll
        for (int j = 0; j < 4; ++j) {
            uint32_t c    = (uint32_t)c0 + (uint32_t)j;
            uint32_t bits = threefry_bits(base + c);
            int a = (j==0)?a4.x:(j==1)?a4.y:(j==2)?a4.z:a4.w;
            if (a > 0) {
                int i = atomicAdd(&s_np, 1);
                if (i < MAXP) s_posRaw[i] = (unsigned short)c;
            } else if (bits < BITSCUT) {
                int i = atomicAdd(&s_nc, 1);
                if (i < MAXC)
                    s_cand[i] = ((unsigned long long)(bits >> 9) << 32) | c;
            }
        }
    }
    __syncthreads();

    const int np   = min(s_np, MAXP);
    const int nc   = min(s_nc, MAXC);
    const int k    = np;               // k = min(num_pos, num_neg) = num_pos
    const int ksel = min(k, nc);

    // exact rank-select: write each of the k smallest (key,col) at its rank
    if (k > 0 && tid < nc) {
        unsigned long long v = s_cand[tid];
        int rank = 0;
        for (int j = 0; j < nc; ++j) rank += (s_cand[j] < v);
        if (rank < k) s_sel[rank] = (unsigned short)(v & 0xFFFFu);
    }
    // deterministic positive ordering (sorted by column; cols are unique)
    if (tid < np) {
        unsigned short c = s_posRaw[tid];
        int rank = 0;
        for (int j = 0; j < np; ++j) rank += (s_posRaw[j] < c);
        s_pos[rank] = c;
    }
    __syncthreads();

    // cosine sims (one warp per entity row)
    for (int s = warpId; s < ksel; s += 8) {
        int col = s_sel[s];
        float2 v = ((const float2*)ent)[(size_t)col * 32 + lane];
        float dot = v.x * s_it[2*lane] + v.y * s_it[2*lane + 1];
        float ssq = v.x * v.x + v.y * v.y;
        #pragma unroll
        for (int o = 16; o; o >>= 1) {
            dot += __shfl_down_sync(0xffffffffu, dot, o);
            ssq += __shfl_down_sync(0xffffffffu, ssq, o);
        }
        if (lane == 0) s_simN[s] = dot / sqrtf(ssq);
    }
    for (int s = warpId; s < np; s += 8) {
        int col = s_pos[s];
        float2 v = ((const float2*)ent)[(size_t)col * 32 + lane];
        float dot = v.x * s_it[2*lane] + v.y * s_it[2*lane + 1];
        float ssq = v.x * v.x + v.y * v.y;
        #pragma unroll
        for (int o = 16; o; o >>= 1) {
            dot += __shfl_down_sync(0xffffffffu, dot, o);
            ssq += __shfl_down_sync(0xffffffffu, ssq, o);
        }
        if (lane == 0) s_simP[s] = dot / sqrtf(ssq);
    }
    __syncthreads();

    // m and S over sampled negatives (warp 0)
    if (warpId == 0 && ksel > 0) {
        float mm = -INFINITY;
        for (int s = lane; s < ksel; s += 32) mm = fmaxf(mm, s_simN[s]);
        #pragma unroll
        for (int o = 16; o; o >>= 1) mm = fmaxf(mm, __shfl_down_sync(0xffffffffu, mm, o));
        mm = __shfl_sync(0xffffffffu, mm, 0);
        float Ss = 0.0f;
        for (int s = lane; s < ksel; s += 32) Ss += expf(s_simN[s] - mm);
        #pragma unroll
        for (int o = 16; o; o >>= 1) Ss += __shfl_down_sync(0xffffffffu, Ss, o);
        if (lane == 0) { s_mS[0] = mm; s_mS[1] = Ss; }
    }
    __syncthreads();

    // per-pair CE, row sum (warp 0) -> per-row globals
    if (warpId == 0) {
        float acc = 0.0f;
        if (np > 0 && ksel > 0) {
            float m = s_mS[0], S = s_mS[1];
            for (int i = lane; i < np; i += 32) {
                float sp = s_simP[i];
                float pm = fmaxf(sp, m);
                acc += logf(expf(sp - pm) + S * expf(m - pm)) + pm - sp;
            }
        }
        #pragma unroll
        for (int o = 16; o; o >>= 1) acc += __shfl_down_sync(0xffffffffu, acc, o);
        if (lane == 0) {
            g_rowLoss[row]  = (double)acc;
            g_rowPairs[row] = (np > 0 && ksel > 0) ? np : 0;
        }
    }

    // ---- last-CTA deterministic reduction --------------------------------
    if (tid == 0) {
        __threadfence();
        unsigned int t = atomicAdd(&g_done, 1u);
        s_last = (t == (unsigned int)(gridDim.x - 1));
    }
    __syncthreads();
    if (s_last) {
        double tsum = 0.0; long long psum = 0;
        for (int i = tid; i < I; i += 256) {
            tsum += g_rowLoss[i];
            psum += (long long)g_rowPairs[i];
        }
        s_red[tid] = tsum; s_redp[tid] = psum;
        __syncthreads();
        for (int o = 128; o; o >>= 1) {
            if (tid < o) {
                s_red[tid]  += s_red[tid + o];
                s_redp[tid] += s_redp[tid + o];
            }
            __syncthreads();
        }
        if (tid == 0) {
            out[0] = (s_redp[0] > 0) ? (float)(s_red[0] / (double)s_redp[0]) : 0.0f;
            g_done = 0;   // reset for next graph replay
        }
    }
}

extern "C" void kernel_launch(void* const* d_in, const int* in_sizes, int n_in,
                              void* d_out, int out_size) {
    const float* item = (const float*)d_in[0];
    const float* ent  = (const float*)d_in[1];
    const int*   adj  = (const int*)d_in[2];
    float* out = (float*)d_out;
    int I = in_sizes[0] / 64;
    int E = in_sizes[1] / 64;
    infonce_row<<<I, 256>>>(item, ent, adj, out, E, I);
}

// round 7
// speedup vs baseline: 1.2003x; 1.0069x over previous
#include <cuda_runtime.h>
#include <stdint.h>

// InfoNCE loss with exact JAX partitionable threefry2x32-20 sampling.
// bits[p] = x0 ^ x1 of threefry2x32(key=(0,42), counter=(0, p)), p = row*E+col.
// Single fused kernel; last-CTA deterministic reduction.
//
// Perf: the kernel is ALU-pipe bound (SHF+LOP3 are ALU-only). All integer adds
// in the threefry core are forced to IMAD (fma pipe) via mad.lo.u32 with an
// opaque multiplier 'one', offloading ~14 ops/call from the saturated ALU pipe.

#define TEMP    0.07f
#define MAXC    256        // candidate buffer (E[nc]~128 at u<1/128, 11-sigma)
#define MAXP    128        // positives per row (expected ~33)
#define BITSCUT (1u << 25) // bits < 2^25  <=>  u < 1/128
#define NROWS   4096

static __device__ double g_rowLoss[NROWS];
static __device__ int    g_rowPairs[NROWS];
static __device__ unsigned int g_done = 0;

__device__ __forceinline__ uint32_t rotl32(uint32_t v, int r) {
    return __funnelshift_l(v, v, r);
}

// d = a + b, forced onto the FMA pipe as IMAD (one is opaque, value 1).
#define MADD(d, a, b) \
    asm("mad.lo.u32 %0, %1, %2, %3;" : "=r"(d) : "r"(a), "r"(one), "r"(b))

// One threefry round: x0 += x1 (IMAD);  x1 = rotl(x1,r) ^ x0 (SHF+LOP3).
#define TF_ROUND(x0, x1, r) do {       \
    MADD(x0, x0, x1);                  \
    x1 = rotl32(x1, r) ^ x0;           \
} while (0)

// Threefry-2x32, 20 rounds, key=(0,42), counter=(0,p). Returns x0out ^ x1out.
__device__ __forceinline__ uint32_t threefry_bits(uint32_t p, uint32_t one) {
    const uint32_t ks1   = 42u;
    const uint32_t ks2   = 0x1BD11BDAu ^ 42u;
    const uint32_t ks2p1 = ks2 + 1u;
    const uint32_t ks1p3 = ks1 + 3u;
    const uint32_t ks2p4 = ks2 + 4u;
    uint32_t x0, x1;
    MADD(x1, p, ks1);            // x1 = p + ks1
    x0 = x1;                     // round 1's x0 += x1 from x0=0
    x1 = rotl32(x1, 13) ^ x0;
    TF_ROUND(x0, x1, 15); TF_ROUND(x0, x1, 26); TF_ROUND(x0, x1, 6);
    MADD(x0, x0, ks1); MADD(x1, x1, ks2p1);
    TF_ROUND(x0, x1, 17); TF_ROUND(x0, x1, 29);
    TF_ROUND(x0, x1, 16); TF_ROUND(x0, x1, 24);
    { uint32_t two = one + one;  // 2, still opaque
      MADD(x0, x0, ks2); MADD(x1, x1, two); }
    TF_ROUND(x0, x1, 13); TF_ROUND(x0, x1, 15);
    TF_ROUND(x0, x1, 26); TF_ROUND(x0, x1, 6);
    MADD(x1, x1, ks1p3);         // x0 += ks0(=0): no-op
    TF_ROUND(x0, x1, 17); TF_ROUND(x0, x1, 29);
    TF_ROUND(x0, x1, 16); TF_ROUND(x0, x1, 24);
    MADD(x0, x0, ks1); MADD(x1, x1, ks2p4);
    TF_ROUND(x0, x1, 13); TF_ROUND(x0, x1, 15);
    TF_ROUND(x0, x1, 26); TF_ROUND(x0, x1, 6);
    { uint32_t five = (one << 2) + one;  // 5, opaque
      MADD(x0, x0, ks2); MADD(x1, x1, five); }
    return x0 ^ x1;
}

__global__ __launch_bounds__(256)
void infonce_row(const float* __restrict__ item,
                 const float* __restrict__ ent,
                 const int*   __restrict__ adj,
                 float* __restrict__ out,
                 int E, int I)
{
    __shared__ float              s_it[64];         // item row * 1/(||it||*T)
    __shared__ unsigned long long s_cand[MAXC];     // (key23<<32)|col
    __shared__ unsigned short     s_posRaw[MAXP];
    __shared__ unsigned short     s_pos[MAXP];      // positives, sorted by col
    __shared__ unsigned short     s_sel[MAXP];      // selected negs, by rank
    __shared__ float              s_simN[MAXP];
    __shared__ float              s_simP[MAXP];
    __shared__ int                s_np, s_nc, s_last;
    __shared__ float              s_mS[2];
    __shared__ double             s_red[256];
    __shared__ long long          s_redp[256];

    const int tid    = threadIdx.x;
    const int lane   = tid & 31;
    const int warpId = tid >> 5;
    const int row    = blockIdx.x;
    const uint32_t one = (E > 0) ? 1u : 0u;   // opaque 1: forces IMAD emission

    if (tid == 0) { s_np = 0; s_nc = 0; }
    if (tid < 64) s_it[tid] = item[(size_t)row * 64 + tid];
    __syncthreads();
    if (tid < 32) {
        float a = s_it[lane], b = s_it[lane + 32];
        float ss = a * a + b * b;
        #pragma unroll
        for (int o = 16; o; o >>= 1) ss += __shfl_down_sync(0xffffffffu, ss, o);
        ss = __shfl_sync(0xffffffffu, ss, 0);
        float sc = 1.0f / (sqrtf(ss) * TEMP);
        s_it[lane]      = a * sc;
        s_it[lane + 32] = b * sc;
    }
    __syncthreads();

    const uint32_t base = (uint32_t)row * (uint32_t)E;
    const int* adjR = adj + (size_t)row * E;

    // ---- streaming pass: threefry + adj scan (4 independent chains/thread) --
    #pragma unroll 1
    for (int c0 = tid * 4; c0 < E; c0 += 1024) {
        int4 a4 = *(const int4*)(adjR + c0);
        #pragma unroll
        for (int j = 0; j < 4; ++j) {
            uint32_t c    = (uint32_t)c0 + (uint32_t)j;
            uint32_t bits = threefry_bits(base + c, one);
            int a = (j==0)?a4.x:(j==1)?a4.y:(j==2)?a4.z:a4.w;
            if (a > 0) {
                int i = atomicAdd(&s_np, 1);
                if (i < MAXP) s_posRaw[i] = (unsigned short)c;
            } else if (bits < BITSCUT) {
                int i = atomicAdd(&s_nc, 1);
                if (i < MAXC)
                    s_cand[i] = ((unsigned long long)(bits >> 9) << 32) | c;
            }
        }
    }
    __syncthreads();

    const int np   = min(s_np, MAXP);
    const int nc   = min(s_nc, MAXC);
    const int k    = np;               // k = min(num_pos, num_neg) = num_pos
    const int ksel = min(k, nc);

    // exact rank-select: write each of the k smallest (key,col) at its rank
    if (k > 0 && tid < nc) {
        unsigned long long v = s_cand[tid];
        int rank = 0;
        for (int j = 0; j < nc; ++j) rank += (s_cand[j] < v);
        if (rank < k) s_sel[rank] = (unsigned short)(v & 0xFFFFu);
    }
    // deterministic positive ordering (sorted by column; cols are unique)
    if (tid < np) {
        unsigned short c = s_posRaw[tid];
        int rank = 0;
        for (int j = 0; j < np; ++j) rank += (s_posRaw[j] < c);
        s_pos[rank] = c;
    }
    __syncthreads();

    // cosine sims (one warp per entity row)
    for (int s = warpId; s < ksel; s += 8) {
        int col = s_sel[s];
        float2 v = ((const float2*)ent)[(size_t)col * 32 + lane];
        float dot = v.x * s_it[2*lane] + v.y * s_it[2*lane + 1];
        float ssq = v.x * v.x + v.y * v.y;
        #pragma unroll
        for (int o = 16; o; o >>= 1) {
            dot += __shfl_down_sync(0xffffffffu, dot, o);
            ssq += __shfl_down_sync(0xffffffffu, ssq, o);
        }
        if (lane == 0) s_simN[s] = dot / sqrtf(ssq);
    }
    for (int s = warpId; s < np; s += 8) {
        int col = s_pos[s];
        float2 v = ((const float2*)ent)[(size_t)col * 32 + lane];
        float dot = v.x * s_it[2*lane] + v.y * s_it[2*lane + 1];
        float ssq = v.x * v.x + v.y * v.y;
        #pragma unroll
        for (int o = 16; o; o >>= 1) {
            dot += __shfl_down_sync(0xffffffffu, dot, o);
            ssq += __shfl_down_sync(0xffffffffu, ssq, o);
        }
        if (lane == 0) s_simP[s] = dot / sqrtf(ssq);
    }
    __syncthreads();

    // m and S over sampled negatives (warp 0)
    if (warpId == 0 && ksel > 0) {
        float mm = -INFINITY;
        for (int s = lane; s < ksel; s += 32) mm = fmaxf(mm, s_simN[s]);
        #pragma unroll
        for (int o = 16; o; o >>= 1) mm = fmaxf(mm, __shfl_down_sync(0xffffffffu, mm, o));
        mm = __shfl_sync(0xffffffffu, mm, 0);
        float Ss = 0.0f;
        for (int s = lane; s < ksel; s += 32) Ss += expf(s_simN[s] - mm);
        #pragma unroll
        for (int o = 16; o; o >>= 1) Ss += __shfl_down_sync(0xffffffffu, Ss, o);
        if (lane == 0) { s_mS[0] = mm; s_mS[1] = Ss; }
    }
    __syncthreads();

    // per-pair CE, row sum (warp 0) -> per-row globals
    if (warpId == 0) {
        float acc = 0.0f;
        if (np > 0 && ksel > 0) {
            float m = s_mS[0], S = s_mS[1];
            for (int i = lane; i < np; i += 32) {
                float sp = s_simP[i];
                float pm = fmaxf(sp, m);
                acc += logf(expf(sp - pm) + S * expf(m - pm)) + pm - sp;
            }
        }
        #pragma unroll
        for (int o = 16; o; o >>= 1) acc += __shfl_down_sync(0xffffffffu, acc, o);
        if (lane == 0) {
            g_rowLoss[row]  = (double)acc;
            g_rowPairs[row] = (np > 0 && ksel > 0) ? np : 0;
        }
    }

    // ---- last-CTA deterministic reduction --------------------------------
    if (tid == 0) {
        __threadfence();
        unsigned int t = atomicAdd(&g_done, 1u);
        s_last = (t == (unsigned int)(gridDim.x - 1));
    }
    __syncthreads();
    if (s_last) {
        double tsum = 0.0; long long psum = 0;
        for (int i = tid; i < I; i += 256) {
            tsum += g_rowLoss[i];
            psum += (long long)g_rowPairs[i];
        }
        s_red[tid] = tsum; s_redp[tid] = psum;
        __syncthreads();
        for (int o = 128; o; o >>= 1) {
            if (tid < o) {
                s_red[tid]  += s_red[tid + o];
                s_redp[tid] += s_redp[tid + o];
            }
            __syncthreads();
        }
        if (tid == 0) {
            out[0] = (s_redp[0] > 0) ? (float)(s_red[0] / (double)s_redp[0]) : 0.0f;
            g_done = 0;   // reset for next graph replay
        }
    }
}

extern "C" void kernel_launch(void* const* d_in, const int* in_sizes, int n_in,
                              void* d_out, int out_size) {
    const float* item = (const float*)d_in[0];
    const float* ent  = (const float*)d_in[1];
    const int*   adj  = (const int*)d_in[2];
    float* out = (float*)d_out;
    int I = in_sizes[0] / 64;
    int E = in_sizes[1] / 64;
    infonce_row<<<I, 256>>>(item, ent, adj, out, E, I);
}

// round 8
// speedup vs baseline: 1.2088x; 1.0071x over previous
#include <cuda_runtime.h>
#include <stdint.h>

// InfoNCE loss with exact JAX partitionable threefry2x32-20 sampling.
// bits[p] = x0 ^ x1 of threefry2x32(key=(0,42), counter=(0, p)), p = row*E+col.
// Single fused kernel; last-CTA deterministic reduction.
//
// Perf: issue-slot-bound. Threefry is written so ptxas can fuse each x0 key
// injection into the adjacent round's accumulate as one IADD3 (x0 += x1 + ks),
// and the rare-event tests (positive / candidate) are batched 8-wide via
// or-reduce + min-reduce with a single combined branch.

#define TEMP    0.07f
#define MAXC    256        // candidate buffer (E[nc]~128 at u<1/128, 11-sigma)
#define MAXP    128        // positives per row (expected ~33)
#define BITSCUT (1u << 25) // bits < 2^25  <=>  u < 1/128
#define NROWS   4096

static __device__ double g_rowLoss[NROWS];
static __device__ int    g_rowPairs[NROWS];
static __device__ unsigned int g_done = 0;

__device__ __forceinline__ uint32_t rotl32(uint32_t v, int r) {
    return __funnelshift_l(v, v, r);
}

// Threefry-2x32, 20 rounds, key=(0,42), counter=(0,p).
// xin must be p + 42 (= p + ks1, caller folds). Returns x0out ^ x1out.
__device__ __forceinline__ uint32_t threefry_bits(uint32_t xin) {
    const uint32_t ks1 = 42u;
    const uint32_t ks2 = 0x1BD11BDAu ^ 42u;
    uint32_t x1 = xin;
    uint32_t x0 = x1;                       // round 1 add from x0=0
    x1 = rotl32(x1, 13) ^ x0;
    x0 += x1;        x1 = rotl32(x1, 15) ^ x0;
    x0 += x1;        x1 = rotl32(x1, 26) ^ x0;
    x0 += x1;        x1 = rotl32(x1,  6) ^ x0;
    x1 += ks2 + 1u;                         // x1 injection first, then
    x0 += x1 + ks1;  x1 = rotl32(x1, 17) ^ x0;   // x0 injection folded (IADD3)
    x0 += x1;        x1 = rotl32(x1, 29) ^ x0;
    x0 += x1;        x1 = rotl32(x1, 16) ^ x0;
    x0 += x1;        x1 = rotl32(x1, 24) ^ x0;
    x1 += 2u;
    x0 += x1 + ks2;  x1 = rotl32(x1, 13) ^ x0;
    x0 += x1;        x1 = rotl32(x1, 15) ^ x0;
    x0 += x1;        x1 = rotl32(x1, 26) ^ x0;
    x0 += x1;        x1 = rotl32(x1,  6) ^ x0;
    x1 += ks1 + 3u;                         // x0 += ks0(=0): nothing
    x0 += x1;        x1 = rotl32(x1, 17) ^ x0;
    x0 += x1;        x1 = rotl32(x1, 29) ^ x0;
    x0 += x1;        x1 = rotl32(x1, 16) ^ x0;
    x0 += x1;        x1 = rotl32(x1, 24) ^ x0;
    x1 += ks2 + 4u;
    x0 += x1 + ks1;  x1 = rotl32(x1, 13) ^ x0;
    x0 += x1;        x1 = rotl32(x1, 15) ^ x0;
    x0 += x1;        x1 = rotl32(x1, 26) ^ x0;
    x0 += x1;        x1 = rotl32(x1,  6) ^ x0;
    return (x0 + ks2) ^ (x1 + 5u);
}

__global__ __launch_bounds__(256)
void infonce_row(const float* __restrict__ item,
                 const float* __restrict__ ent,
                 const int*   __restrict__ adj,
                 float* __restrict__ out,
                 int E, int I)
{
    __shared__ float              s_it[64];         // item row * 1/(||it||*T)
    __shared__ unsigned long long s_cand[MAXC];     // (key23<<32)|col
    __shared__ unsigned short     s_posRaw[MAXP];
    __shared__ unsigned short     s_pos[MAXP];      // positives, sorted by col
    __shared__ unsigned short     s_sel[MAXP];      // selected negs, by rank
    __shared__ float              s_simN[MAXP];
    __shared__ float              s_simP[MAXP];
    __shared__ int                s_np, s_nc, s_last;
    __shared__ float              s_mS[2];
    __shared__ double             s_red[256];
    __shared__ long long          s_redp[256];

    const int tid    = threadIdx.x;
    const int lane   = tid & 31;
    const int warpId = tid >> 5;
    const int row    = blockIdx.x;

    if (tid == 0) { s_np = 0; s_nc = 0; }
    if (tid < 64) s_it[tid] = item[(size_t)row * 64 + tid];
    __syncthreads();
    if (tid < 32) {
        float a = s_it[lane], b = s_it[lane + 32];
        float ss = a * a + b * b;
        #pragma unroll
        for (int o = 16; o; o >>= 1) ss += __shfl_down_sync(0xffffffffu, ss, o);
        ss = __shfl_sync(0xffffffffu, ss, 0);
        float sc = 1.0f / (sqrtf(ss) * TEMP);
        s_it[lane]      = a * sc;
        s_it[lane + 32] = b * sc;
    }
    __syncthreads();

    const uint32_t base = (uint32_t)row * (uint32_t)E;
    const int* adjR = adj + (size_t)row * E;

    // ---- streaming pass: threefry + adj scan, 8 elements/thread/iter ------
    #pragma unroll 1
    for (int c0 = tid * 8; c0 < E; c0 += 2048) {
        const int4 a4a = *(const int4*)(adjR + c0);
        const int4 a4b = *(const int4*)(adjR + c0 + 4);
        const uint32_t pb42 = base + (uint32_t)c0 + 42u;   // p + ks1 base
        uint32_t b[8];
        #pragma unroll
        for (int j = 0; j < 8; ++j) b[j] = threefry_bits(pb42 + (uint32_t)j);

        int aor = a4a.x | a4a.y | a4a.z | a4a.w
                | a4b.x | a4b.y | a4b.z | a4b.w;
        uint32_t bmin = min(min(min(b[0], b[1]), min(b[2], b[3])),
                            min(min(b[4], b[5]), min(b[6], b[7])));
        if ((aor > 0) | (bmin < BITSCUT)) {      // rare (~8%)
            #pragma unroll
            for (int j = 0; j < 8; ++j) {
                int a = (j==0)?a4a.x:(j==1)?a4a.y:(j==2)?a4a.z:(j==3)?a4a.w:
                        (j==4)?a4b.x:(j==5)?a4b.y:(j==6)?a4b.z:a4b.w;
                uint32_t c = (uint32_t)c0 + (uint32_t)j;
                if (a > 0) {
                    int i = atomicAdd(&s_np, 1);
                    if (i < MAXP) s_posRaw[i] = (unsigned short)c;
                } else if (b[j] < BITSCUT) {
                    int i = atomicAdd(&s_nc, 1);
                    if (i < MAXC)
                        s_cand[i] = ((unsigned long long)(b[j] >> 9) << 32) | c;
                }
            }
        }
    }
    __syncthreads();

    const int np   = min(s_np, MAXP);
    const int nc   = min(s_nc, MAXC);
    const int k    = np;               // k = min(num_pos, num_neg) = num_pos
    const int ksel = min(k, nc);

    // exact rank-select: write each of the k smallest (key,col) at its rank
    if (k > 0 && tid < nc) {
        unsigned long long v = s_cand[tid];
        int rank = 0;
        for (int j = 0; j < nc; ++j) rank += (s_cand[j] < v);
        if (rank < k) s_sel[rank] = (unsigned short)(v & 0xFFFFu);
    }
    // deterministic positive ordering (sorted by column; cols are unique)
    if (tid < np) {
        unsigned short c = s_posRaw[tid];
        int rank = 0;
        for (int j = 0; j < np; ++j) rank += (s_posRaw[j] < c);
        s_pos[rank] = c;
    }
    __syncthreads();

    // cosine sims (one warp per entity row)
    for (int s = warpId; s < ksel; s += 8) {
        int col = s_sel[s];
        float2 v = ((const float2*)ent)[(size_t)col * 32 + lane];
        float dot = v.x * s_it[2*lane] + v.y * s_it[2*lane + 1];
        float ssq = v.x * v.x + v.y * v.y;
        #pragma unroll
        for (int o = 16; o; o >>= 1) {
            dot += __shfl_down_sync(0xffffffffu, dot, o);
            ssq += __shfl_down_sync(0xffffffffu, ssq, o);
        }
        if (lane == 0) s_simN[s] = dot / sqrtf(ssq);
    }
    for (int s = warpId; s < np; s += 8) {
        int col = s_pos[s];
        float2 v = ((const float2*)ent)[(size_t)col * 32 + lane];
        float dot = v.x * s_it[2*lane] + v.y * s_it[2*lane + 1];
        float ssq = v.x * v.x + v.y * v.y;
        #pragma unroll
        for (int o = 16; o; o >>= 1) {
            dot += __shfl_down_sync(0xffffffffu, dot, o);
            ssq += __shfl_down_sync(0xffffffffu, ssq, o);
        }
        if (lane == 0) s_simP[s] = dot / sqrtf(ssq);
    }
    __syncthreads();

    // m and S over sampled negatives (warp 0)
    if (warpId == 0 && ksel > 0) {
        float mm = -INFINITY;
        for (int s = lane; s < ksel; s += 32) mm = fmaxf(mm, s_simN[s]);
        #pragma unroll
        for (int o = 16; o; o >>= 1) mm = fmaxf(mm, __shfl_down_sync(0xffffffffu, mm, o));
        mm = __shfl_sync(0xffffffffu, mm, 0);
        float Ss = 0.0f;
        for (int s = lane; s < ksel; s += 32) Ss += expf(s_simN[s] - mm);
        #pragma unroll
        for (int o = 16; o; o >>= 1) Ss += __shfl_down_sync(0xffffffffu, Ss, o);
        if (lane == 0) { s_mS[0] = mm; s_mS[1] = Ss; }
    }
    __syncthreads();

    // per-pair CE, row sum (warp 0) -> per-row globals
    if (warpId == 0) {
        float acc = 0.0f;
        if (np > 0 && ksel > 0) {
            float m = s_mS[0], S = s_mS[1];
            for (int i = lane; i < np; i += 32) {
                float sp = s_simP[i];
                float pm = fmaxf(sp, m);
                acc += logf(expf(sp - pm) + S * expf(m - pm)) + pm - sp;
            }
        }
        #pragma unroll
        for (int o = 16; o; o >>= 1) acc += __shfl_down_sync(0xffffffffu, acc, o);
        if (lane == 0) {
            g_rowLoss[row]  = (double)acc;
            g_rowPairs[row] = (np > 0 && ksel > 0) ? np : 0;
        }
    }

    // ---- last-CTA deterministic reduction --------------------------------
    if (tid == 0) {
        __threadfence();
        unsigned int t = atomicAdd(&g_done, 1u);
        s_last = (t == (unsigned int)(gridDim.x - 1));
    }
    __syncthreads();
    if (s_last) {
        double tsum = 0.0; long long psum = 0;
        for (int i = tid; i < I; i += 256) {
            tsum += g_rowLoss[i];
            psum += (long long)g_rowPairs[i];
        }
        s_red[tid] = tsum; s_redp[tid] = psum;
        __syncthreads();
        for (int o = 128; o; o >>= 1) {
            if (tid < o) {
                s_red[tid]  += s_red[tid + o];
                s_redp[tid] += s_redp[tid + o];
            }
            __syncthreads();
        }
        if (tid == 0) {
            out[0] = (s_redp[0] > 0) ? (float)(s_red[0] / (double)s_redp[0]) : 0.0f;
            g_done = 0;   // reset for next graph replay
        }
    }
}

extern "C" void kernel_launch(void* const* d_in, const int* in_sizes, int n_in,
                              void* d_out, int out_size) {
    const float* item = (const float*)d_in[0];
    const float* ent  = (const float*)d_in[1];
    const int*   adj  = (const int*)d_in[2];
    float* out = (float*)d_out;
    int I = in_sizes[0] / 64;
    int E = in_sizes[1] / 64;
    infonce_row<<<I, 256>>>(item, ent, adj, out, E, I);
}

// round 9
// speedup vs baseline: 1.2415x; 1.0271x over previous
#include <cuda_runtime.h>
#include <stdint.h>

// InfoNCE loss with exact JAX partitionable threefry2x32-20 sampling.
// bits[p] = x0 ^ x1 of threefry2x32(key=(0,42), counter=(0, p)), p = row*E+col.
// Single fused kernel; last-CTA deterministic reduction.
//
// Perf: issue-bubble-bound (issue pinned ~78% across pipe mixes). The streaming
// loop is fully BRANCH-FREE: per element one predicated asm block pushes hits
// (positives: sentinel key 0xFFFFFFFF; candidates: raw bits) into a unified
// 64-bit shared buffer via predicated shared atomics. No BSSY/BSYNC regions.
// Selection ranks the ~160 entries once: candidates occupy ranks [0,ncand),
// positives [ncand,n) sorted by column.

#define TEMP    0.07f
#define MAXB    384        // unified buffer: E[n]~161 (128 cand + 33 pos), >15 sigma
#define MAXP    128        // positives per row (expected ~33)
#define BITSCUT (1u << 25) // bits < 2^25  <=>  u < 1/128
#define NROWS   4096

static __device__ double g_rowLoss[NROWS];
static __device__ int    g_rowPairs[NROWS];
static __device__ unsigned int g_done = 0;

__device__ __forceinline__ uint32_t rotl32(uint32_t v, int r) {
    return __funnelshift_l(v, v, r);
}

// Threefry-2x32, 20 rounds, key=(0,42), counter=(0,p).
// xin must be p + 42 (= p + ks1, caller folds). Returns x0out ^ x1out.
__device__ __forceinline__ uint32_t threefry_bits(uint32_t xin) {
    const uint32_t ks1 = 42u;
    const uint32_t ks2 = 0x1BD11BDAu ^ 42u;
    uint32_t x1 = xin;
    uint32_t x0 = x1;                       // round 1 add from x0=0
    x1 = rotl32(x1, 13) ^ x0;
    x0 += x1;        x1 = rotl32(x1, 15) ^ x0;
    x0 += x1;        x1 = rotl32(x1, 26) ^ x0;
    x0 += x1;        x1 = rotl32(x1,  6) ^ x0;
    x1 += ks2 + 1u;                         // x1 injection, then x0 inj folds:
    x0 += x1 + ks1;  x1 = rotl32(x1, 17) ^ x0;
    x0 += x1;        x1 = rotl32(x1, 29) ^ x0;
    x0 += x1;        x1 = rotl32(x1, 16) ^ x0;
    x0 += x1;        x1 = rotl32(x1, 24) ^ x0;
    x1 += 2u;
    x0 += x1 + ks2;  x1 = rotl32(x1, 13) ^ x0;
    x0 += x1;        x1 = rotl32(x1, 15) ^ x0;
    x0 += x1;        x1 = rotl32(x1, 26) ^ x0;
    x0 += x1;        x1 = rotl32(x1,  6) ^ x0;
    x1 += ks1 + 3u;                         // x0 += ks0(=0): nothing
    x0 += x1;        x1 = rotl32(x1, 17) ^ x0;
    x0 += x1;        x1 = rotl32(x1, 29) ^ x0;
    x0 += x1;        x1 = rotl32(x1, 16) ^ x0;
    x0 += x1;        x1 = rotl32(x1, 24) ^ x0;
    x1 += ks2 + 4u;
    x0 += x1 + ks1;  x1 = rotl32(x1, 13) ^ x0;
    x0 += x1;        x1 = rotl32(x1, 15) ^ x0;
    x0 += x1;        x1 = rotl32(x1, 26) ^ x0;
    x0 += x1;        x1 = rotl32(x1,  6) ^ x0;
    return (x0 + ks2) ^ (x1 + 5u);
}

// Branch-free hit push: if (a>0 || bits<BITSCUT), append {col, a>0?MAX:bits}
// to the unified shared buffer via predicated shared atomic + store.
__device__ __forceinline__ void push_hit(int a, uint32_t bits, uint32_t col,
                                         uint32_t ctr_addr, uint32_t buf_addr) {
    asm volatile(
        "{\n\t"
        ".reg .pred p1, p, pb;\n\t"
        ".reg .u32 v, idx, adr;\n\t"
        "mov.u32 idx, 0;\n\t"
        "setp.gt.s32 p1, %0, 0;\n\t"
        "setp.lt.or.u32 p, %1, %2, p1;\n\t"
        "selp.b32 v, 0xFFFFFFFF, %1, p1;\n\t"
        "@p atom.shared.add.u32 idx, [%3], 1;\n\t"
        "setp.lt.and.u32 pb, idx, %4, p;\n\t"
        "mad.lo.u32 adr, idx, 8, %5;\n\t"
        "@pb st.shared.v2.u32 [adr], {%6, v};\n\t"
        "}"
        :: "r"(a), "r"(bits), "r"(BITSCUT), "r"(ctr_addr),
           "r"((uint32_t)MAXB), "r"(buf_addr), "r"(col)
        : "memory");
}

__global__ __launch_bounds__(256)
void infonce_row(const float* __restrict__ item,
                 const float* __restrict__ ent,
                 const int*   __restrict__ adj,
                 float* __restrict__ out,
                 int E, int I)
{
    __shared__ float              s_it[64];        // item row * 1/(||it||*T)
    __shared__ unsigned long long s_buf[MAXB];     // {col(lo32), key(hi32)}
    __shared__ unsigned short     s_pos[MAXP];     // positives, sorted by col
    __shared__ unsigned short     s_sel[MAXP];     // selected negs, by rank
    __shared__ float              s_simN[MAXP];
    __shared__ float              s_simP[MAXP];
    __shared__ int                s_n, s_last;
    __shared__ float              s_mS[2];
    __shared__ double             s_red[256];
    __shared__ long long          s_redp[256];

    const int tid    = threadIdx.x;
    const int lane   = tid & 31;
    const int warpId = tid >> 5;
    const int row    = blockIdx.x;

    const uint32_t ctr_addr = (uint32_t)__cvta_generic_to_shared(&s_n);
    const uint32_t buf_addr = (uint32_t)__cvta_generic_to_shared(&s_buf[0]);

    if (tid == 0) s_n = 0;
    if (tid < 64) s_it[tid] = item[(size_t)row * 64 + tid];
    __syncthreads();
    if (tid < 32) {
        float a = s_it[lane], b = s_it[lane + 32];
        float ss = a * a + b * b;
        #pragma unroll
        for (int o = 16; o; o >>= 1) ss += __shfl_down_sync(0xffffffffu, ss, o);
        ss = __shfl_sync(0xffffffffu, ss, 0);
        float sc = 1.0f / (sqrtf(ss) * TEMP);
        s_it[lane]      = a * sc;
        s_it[lane + 32] = b * sc;
    }
    __syncthreads();

    const uint32_t base = (uint32_t)row * (uint32_t)E;
    const int* adjR = adj + (size_t)row * E;

    // ---- streaming pass: threefry + adj scan, branch-free, 8 elem/iter ----
    #pragma unroll 1
    for (int c0 = tid * 8; c0 < E; c0 += 2048) {
        const int4 a4a = *(const int4*)(adjR + c0);
        const int4 a4b = *(const int4*)(adjR + c0 + 4);
        const uint32_t pb42 = base + (uint32_t)c0 + 42u;   // p + ks1 base
        #pragma unroll
        for (int j = 0; j < 8; ++j) {
            uint32_t bits = threefry_bits(pb42 + (uint32_t)j);
            int a = (j==0)?a4a.x:(j==1)?a4a.y:(j==2)?a4a.z:(j==3)?a4a.w:
                    (j==4)?a4b.x:(j==5)?a4b.y:(j==6)?a4b.z:a4b.w;
            push_hit(a, bits, (uint32_t)c0 + (uint32_t)j, ctr_addr, buf_addr);
        }
    }
    __syncthreads();

    // ---- selection: one rank pass over unified buffer --------------------
    const int n = min(s_n, MAXB);
    bool isP = false; uint32_t hi = 0, col = 0;
    if (tid < n) {
        unsigned long long e = s_buf[tid];
        hi  = (uint32_t)(e >> 32);
        col = (uint32_t)e & 0xFFFFu;
        isP = (hi == 0xFFFFFFFFu);
    }
    const int npT   = __syncthreads_count(isP);   // total positives
    const int np    = min(npT, MAXP);
    const int k     = np;                 // k = min(num_pos, num_neg) = num_pos
    const int ncand = n - npT;
    const int ksel  = min(k, min(ncand, MAXP));

    // normalize: candidates -> (bits>>9)<<16 | col ; positives -> sentinel
    if (tid < n)
        s_buf[tid] = isP ? ((0x10000ULL << 16) | col)
                         : (((unsigned long long)(hi >> 9)) << 16) | col;
    __syncthreads();
    if (tid < n) {
        unsigned long long v = s_buf[tid];
        int rank = 0;
        for (int j = 0; j < n; ++j) rank += (s_buf[j] < v);
        if (isP) {
            int pr = rank - ncand;                 // positives rank above cands
            if (pr >= 0 && pr < MAXP) s_pos[pr] = (unsigned short)col;
        } else if (rank < ksel) {
            s_sel[rank] = (unsigned short)col;
        }
    }
    __syncthreads();

    // ---- cosine sims (one warp per entity row) ---------------------------
    for (int s = warpId; s < ksel; s += 8) {
        int c = s_sel[s];
        float2 v = ((const float2*)ent)[(size_t)c * 32 + lane];
        float dot = v.x * s_it[2*lane] + v.y * s_it[2*lane + 1];
        float ssq = v.x * v.x + v.y * v.y;
        #pragma unroll
        for (int o = 16; o; o >>= 1) {
            dot += __shfl_down_sync(0xffffffffu, dot, o);
            ssq += __shfl_down_sync(0xffffffffu, ssq, o);
        }
        if (lane == 0) s_simN[s] = dot / sqrtf(ssq);
    }
    for (int s = warpId; s < np; s += 8) {
        int c = s_pos[s];
        float2 v = ((const float2*)ent)[(size_t)c * 32 + lane];
        float dot = v.x * s_it[2*lane] + v.y * s_it[2*lane + 1];
        float ssq = v.x * v.x + v.y * v.y;
        #pragma unroll
        for (int o = 16; o; o >>= 1) {
            dot += __shfl_down_sync(0xffffffffu, dot, o);
            ssq += __shfl_down_sync(0xffffffffu, ssq, o);
        }
        if (lane == 0) s_simP[s] = dot / sqrtf(ssq);
    }
    __syncthreads();

    // ---- m and S over sampled negatives (warp 0) -------------------------
    if (warpId == 0 && ksel > 0) {
        float mm = -INFINITY;
        for (int s = lane; s < ksel; s += 32) mm = fmaxf(mm, s_simN[s]);
        #pragma unroll
        for (int o = 16; o; o >>= 1) mm = fmaxf(mm, __shfl_down_sync(0xffffffffu, mm, o));
        mm = __shfl_sync(0xffffffffu, mm, 0);
        float Ss = 0.0f;
        for (int s = lane; s < ksel; s += 32) Ss += expf(s_simN[s] - mm);
        #pragma unroll
        for (int o = 16; o; o >>= 1) Ss += __shfl_down_sync(0xffffffffu, Ss, o);
        if (lane == 0) { s_mS[0] = mm; s_mS[1] = Ss; }
    }
    __syncthreads();

    // ---- per-pair CE, row sum (warp 0) -> per-row globals ----------------
    if (warpId == 0) {
        float acc = 0.0f;
        if (np > 0 && ksel > 0) {
            float m = s_mS[0], S = s_mS[1];
            for (int i = lane; i < np; i += 32) {
                float sp = s_simP[i];
                float pm = fmaxf(sp, m);
                acc += logf(expf(sp - pm) + S * expf(m - pm)) + pm - sp;
            }
        }
        #pragma unroll
        for (int o = 16; o; o >>= 1) acc += __shfl_down_sync(0xffffffffu, acc, o);
        if (lane == 0) {
            g_rowLoss[row]  = (double)acc;
            g_rowPairs[row] = (np > 0 && ksel > 0) ? np : 0;
        }
    }

    // ---- last-CTA deterministic reduction --------------------------------
    if (tid == 0) {
        __threadfence();
        unsigned int t = atomicAdd(&g_done, 1u);
        s_last = (t == (unsigned int)(gridDim.x - 1));
    }
    __syncthreads();
    if (s_last) {
        double tsum = 0.0; long long psum = 0;
        for (int i = tid; i < I; i += 256) {
            tsum += g_rowLoss[i];
            psum += (long long)g_rowPairs[i];
        }
        s_red[tid] = tsum; s_redp[tid] = psum;
        __syncthreads();
        for (int o = 128; o; o >>= 1) {
            if (tid < o) {
                s_red[tid]  += s_red[tid + o];
                s_redp[tid] += s_redp[tid + o];
            }
            __syncthreads();
        }
        if (tid == 0) {
            out[0] = (s_redp[0] > 0) ? (float)(s_red[0] / (double)s_redp[0]) : 0.0f;
            g_done = 0;   // reset for next graph replay
        }
    }
}

extern "C" void kernel_launch(void* const* d_in, const int* in_sizes, int n_in,
                              void* d_out, int out_size) {
    const float* item = (const float*)d_in[0];
    const float* ent  = (const float*)d_in[1];
    const int*   adj  = (const int*)d_in[2];
    float* out = (float*)d_out;
    int I = in_sizes[0] / 64;
    int E = in_sizes[1] / 64;
    infonce_row<<<I, 256>>>(item, ent, adj, out, E, I);
}